// round 9
// baseline (speedup 1.0000x reference)
#include <cuda_runtime.h>
#include <cuda_bf16.h>
#include <cstdint>

// EfficientReynoldsFeatureOperator:
//   x:  (B=8, N=8192, D=512) fp32
//   W:  (512, 128) fp32, pw: (128) fp32
//   out:(B, N, R) fp32,  out[b,n,r] = (mean_n(x[b]) @ W)[r] * pw[r]
// Using mean_n(x @ W) == (mean_n x) @ W.
//
// Round 8: TMA-read k1 regressed (as did TMA-store in r6) -> all LDG/STG.
// This round: software-pipeline across sequential launches. Batch halves:
//   K1(b0-3) -> k2(b0-3) -> F{ K1(b4-7) || K3-writes(b0-3) } -> k2(b4-7) -> K3(b4-7)
// F's two block groups are fully independent (inputs from prior launches),
// so the b0-3 output writes hide behind the b4-7 DRAM reads. No sync anywhere.

#define B_DIM 8
#define N_DIM 8192
#define D_DIM 512
#define R_DIM 128
#define CHUNKS 256                           // chunks per batch
#define ROWS_PER_CHUNK (N_DIM / CHUNKS)      // 32
#define G2 32                                // k2a groups per batch
#define CHUNKS_PER_G2 (CHUNKS / G2)          // 8
#define HALF_RD_BLOCKS (CHUNKS * 4)          // 1024 reader blocks per half
#define HALF_WR_BLOCKS 512                   // writer blocks per half (32KB each)

__device__ float g_partial[B_DIM * CHUNKS * D_DIM];   // 4 MB scratch (L2-hot)
__device__ float g_p2[B_DIM * G2 * D_DIM];            // 512 KB
__device__ float g_y[B_DIM * R_DIM];                  // 4 KB

// ---------------------------------------------------------------------------
// Reader body (round-4 proven k1): sum 32 rows of batch b, chunk `chunk`.
// 8 back-to-back LDG.128 (__ldcs, evict-first), 2 accumulators, ~64 regs.
// ---------------------------------------------------------------------------
__device__ __forceinline__ void reduce_chunk(const float* __restrict__ x,
                                             int b, int chunk, int t) {
    const float4* xrow = reinterpret_cast<const float4*>(
        x + ((size_t)b * N_DIM + (size_t)chunk * ROWS_PER_CHUNK) * D_DIM);

    float4 a0 = make_float4(0.f, 0.f, 0.f, 0.f);
    float4 a1 = make_float4(0.f, 0.f, 0.f, 0.f);

#pragma unroll
    for (int i = 0; i < ROWS_PER_CHUNK; i += 8) {
        float4 v0 = __ldcs(&xrow[(size_t)(i + 0) * 128 + t]);
        float4 v1 = __ldcs(&xrow[(size_t)(i + 1) * 128 + t]);
        float4 v2 = __ldcs(&xrow[(size_t)(i + 2) * 128 + t]);
        float4 v3 = __ldcs(&xrow[(size_t)(i + 3) * 128 + t]);
        float4 v4 = __ldcs(&xrow[(size_t)(i + 4) * 128 + t]);
        float4 v5 = __ldcs(&xrow[(size_t)(i + 5) * 128 + t]);
        float4 v6 = __ldcs(&xrow[(size_t)(i + 6) * 128 + t]);
        float4 v7 = __ldcs(&xrow[(size_t)(i + 7) * 128 + t]);
        a0.x += v0.x; a0.y += v0.y; a0.z += v0.z; a0.w += v0.w;
        a1.x += v1.x; a1.y += v1.y; a1.z += v1.z; a1.w += v1.w;
        a0.x += v2.x; a0.y += v2.y; a0.z += v2.z; a0.w += v2.w;
        a1.x += v3.x; a1.y += v3.y; a1.z += v3.z; a1.w += v3.w;
        a0.x += v4.x; a0.y += v4.y; a0.z += v4.z; a0.w += v4.w;
        a1.x += v5.x; a1.y += v5.y; a1.z += v5.z; a1.w += v5.w;
        a0.x += v6.x; a0.y += v6.y; a0.z += v6.z; a0.w += v6.w;
        a1.x += v7.x; a1.y += v7.y; a1.z += v7.z; a1.w += v7.w;
    }
    a0.x += a1.x; a0.y += a1.y; a0.z += a1.z; a0.w += a1.w;

    float4* p = reinterpret_cast<float4*>(
        g_partial + ((size_t)b * CHUNKS + chunk) * D_DIM);
    p[t] = a0;
}

// ---------------------------------------------------------------------------
// Writer body: writer task w in [0,512): batch b = b_base + w>>7,
// segment seg = w&127 (32 KB). v is position-invariant: idx&31 == t&31.
// ---------------------------------------------------------------------------
__device__ __forceinline__ void write_segment(float4* __restrict__ out4,
                                              int w, int b_base, int t) {
    const int b   = b_base + (w >> 7);
    const int seg = w & 127;
    const float4* y4 = reinterpret_cast<const float4*>(g_y);
    float4 v = __ldg(&y4[b * (R_DIM / 4) + (t & 31)]);
    float4* dst = out4 + (size_t)b * (N_DIM * R_DIM / 4) + (size_t)seg * 2048;
#pragma unroll
    for (int j = 0; j < 16; ++j)
        dst[(size_t)j * 128 + t] = v;
}

// ---------------------------------------------------------------------------
// K1: reduce 4 batches. grid = (CHUNKS, 4), 128 threads.
// ---------------------------------------------------------------------------
__global__ __launch_bounds__(128, 8) void k1_half(const float* __restrict__ x,
                                                  int b_off) {
    reduce_chunk(x, b_off + blockIdx.y, blockIdx.x, threadIdx.x);
}

// ---------------------------------------------------------------------------
// F: readers for batches 4-7 (blocks 0..1023) + writers for batches 0-3
// (blocks 1024..1535). Both groups' inputs come from PRIOR launches -> no sync.
// ---------------------------------------------------------------------------
__global__ __launch_bounds__(128, 8) void fused_read_write(
    const float* __restrict__ x, float4* __restrict__ out4) {
    const int t = threadIdx.x;
    if (blockIdx.x < HALF_RD_BLOCKS) {
        const int bid = blockIdx.x;
        reduce_chunk(x, 4 + (bid >> 8), bid & (CHUNKS - 1), t);
    } else {
        write_segment(out4, blockIdx.x - HALF_RD_BLOCKS, 0, t);
    }
}

// ---------------------------------------------------------------------------
// K3: final writes for batches 4-7. grid = 512, 128 threads.
// ---------------------------------------------------------------------------
__global__ __launch_bounds__(128, 8) void k3_half(float4* __restrict__ out4) {
    write_segment(out4, blockIdx.x, 4, threadIdx.x);
}

// ---------------------------------------------------------------------------
// K2a: group reduction for 4 batches. grid = (G2, 4), 128 threads.
// ---------------------------------------------------------------------------
__global__ __launch_bounds__(128) void k2a_reduce(int b_off) {
    const int j  = blockIdx.x;
    const int b  = b_off + blockIdx.y;
    const int d4 = threadIdx.x;

    const float4* base = reinterpret_cast<const float4*>(
        g_partial + ((size_t)b * CHUNKS + (size_t)j * CHUNKS_PER_G2) * D_DIM);

    float4 acc = make_float4(0.f, 0.f, 0.f, 0.f);
#pragma unroll
    for (int c = 0; c < CHUNKS_PER_G2; ++c) {
        float4 v = base[(size_t)c * 128 + d4];
        acc.x += v.x; acc.y += v.y; acc.z += v.z; acc.w += v.w;
    }
    float4* p = reinterpret_cast<float4*>(
        g_p2 + ((size_t)b * G2 + j) * D_DIM);
    p[d4] = acc;
}

// ---------------------------------------------------------------------------
// K2b: finish reduction + projection for 4 batches. grid = 4, 512 threads.
// ---------------------------------------------------------------------------
__global__ __launch_bounds__(512) void k2b_finish_and_project(
    const float* __restrict__ W, const float* __restrict__ pw, int b_off) {
    __shared__ float s_part[4][D_DIM];
    __shared__ float s_mean[D_DIM];
    __shared__ float s_red[16][R_DIM];
    const int b = b_off + blockIdx.x;
    const int t = threadIdx.x;
    const int g  = t >> 7;        // 0..3
    const int d4 = t & 127;       // 0..127

    const float4* pbase = reinterpret_cast<const float4*>(
        g_p2 + (size_t)b * G2 * D_DIM);

    float4 acc = make_float4(0.f, 0.f, 0.f, 0.f);
#pragma unroll
    for (int c = g; c < G2; c += 4) {
        float4 v = pbase[(size_t)c * 128 + d4];
        acc.x += v.x; acc.y += v.y; acc.z += v.z; acc.w += v.w;
    }
    s_part[g][4 * d4 + 0] = acc.x;
    s_part[g][4 * d4 + 1] = acc.y;
    s_part[g][4 * d4 + 2] = acc.z;
    s_part[g][4 * d4 + 3] = acc.w;
    __syncthreads();

    s_mean[t] = (s_part[0][t] + s_part[1][t] + s_part[2][t] + s_part[3][t])
                * (1.0f / (float)N_DIM);
    __syncthreads();

    const int w    = t >> 5;
    const int lane = t & 31;
    float acc0 = 0.f, acc1 = 0.f, acc2 = 0.f, acc3 = 0.f;
#pragma unroll
    for (int i = 0; i < 32; ++i) {
        const int d = w * 32 + i;
        const float m = s_mean[d];
        const float* Wr = W + (size_t)d * R_DIM;
        acc0 = fmaf(m, __ldg(&Wr[lane]),      acc0);
        acc1 = fmaf(m, __ldg(&Wr[32 + lane]), acc1);
        acc2 = fmaf(m, __ldg(&Wr[64 + lane]), acc2);
        acc3 = fmaf(m, __ldg(&Wr[96 + lane]), acc3);
    }
    s_red[w][lane]      = acc0;
    s_red[w][32 + lane] = acc1;
    s_red[w][64 + lane] = acc2;
    s_red[w][96 + lane] = acc3;
    __syncthreads();

    if (t < R_DIM) {
        float y = 0.f;
#pragma unroll
        for (int k = 0; k < 16; ++k)
            y += s_red[k][t];
        g_y[b * R_DIM + t] = y * pw[t];
    }
}

// ---------------------------------------------------------------------------
extern "C" void kernel_launch(void* const* d_in, const int* in_sizes, int n_in,
                              void* d_out, int out_size) {
    const float* x  = (const float*)d_in[0];
    const float* W  = (const float*)d_in[1];
    const float* pw = (const float*)d_in[2];
    float4* out4    = (float4*)d_out;

    (void)in_sizes; (void)n_in; (void)out_size;

    // Half 1: reduce b0-3
    k1_half<<<dim3(CHUNKS, 4), 128>>>(x, 0);
    k2a_reduce<<<dim3(G2, 4), 128>>>(0);
    k2b_finish_and_project<<<4, 512>>>(W, pw, 0);

    // Overlap: read b4-7 while writing out b0-3
    fused_read_write<<<HALF_RD_BLOCKS + HALF_WR_BLOCKS, 128>>>(x, out4);

    // Finish b4-7
    k2a_reduce<<<dim3(G2, 4), 128>>>(4);
    k2b_finish_and_project<<<4, 512>>>(W, pw, 4);
    k3_half<<<HALF_WR_BLOCKS, 128>>>(out4);
}

// round 10
// speedup vs baseline: 1.1653x; 1.1653x over previous
#include <cuda_runtime.h>
#include <cuda_bf16.h>
#include <cstdint>

// EfficientReynoldsFeatureOperator:
//   x:  (B=8, N=8192, D=512) fp32
//   W:  (512, 128) fp32, pw: (128) fp32
//   out:(B, N, R) fp32,  out[b,n,r] = (mean_n(x[b]) @ W)[r] * pw[r]
// Using mean_n(x @ W) == (mean_n x) @ W.
//
// Round 9 showed read/write overlap is bandwidth-neutral (shared DRAM/LTS)
// and extra launches cost more than they save. Final structure: 3 launches,
// minimal scratch traffic.
//   k1: 1024 blocks, 64 rows each (proven MLP-8 __ldcs loop) -> 2MB partials
//   k2: 8 blocks, merged two-level reduction + projection (k2a eliminated)
//   k3: proven 8-way ILP STG broadcast (store path wall ~3.7 TB/s, closed)

#define B_DIM 8
#define N_DIM 8192
#define D_DIM 512
#define R_DIM 128
#define CHUNKS 128                           // chunks per batch
#define ROWS_PER_CHUNK (N_DIM / CHUNKS)      // 64

__device__ float g_partial[B_DIM * CHUNKS * D_DIM];   // 2 MB scratch (L2-hot)
__device__ float g_y[B_DIM * R_DIM];                  // 4 KB

// ---------------------------------------------------------------------------
// K1: partial column sums of x over n.
// grid = (CHUNKS, B) = 1024 blocks, 128 threads; thread t owns float4 slot t.
// 64 rows per block, 8 back-to-back LDG.128 per step (MLP_p1=8), 2 accums,
// __ldcs evict-first (x is read-once). Proven 5.75 TB/s body from round 4.
// ---------------------------------------------------------------------------
__global__ __launch_bounds__(128, 8) void k1_colsum_partial(const float* __restrict__ x) {
    const int chunk = blockIdx.x;
    const int b     = blockIdx.y;
    const int t     = threadIdx.x;            // 0..127

    const float4* xrow = reinterpret_cast<const float4*>(
        x + ((size_t)b * N_DIM + (size_t)chunk * ROWS_PER_CHUNK) * D_DIM);

    float4 a0 = make_float4(0.f, 0.f, 0.f, 0.f);
    float4 a1 = make_float4(0.f, 0.f, 0.f, 0.f);

#pragma unroll
    for (int i = 0; i < ROWS_PER_CHUNK; i += 8) {
        float4 v0 = __ldcs(&xrow[(size_t)(i + 0) * 128 + t]);
        float4 v1 = __ldcs(&xrow[(size_t)(i + 1) * 128 + t]);
        float4 v2 = __ldcs(&xrow[(size_t)(i + 2) * 128 + t]);
        float4 v3 = __ldcs(&xrow[(size_t)(i + 3) * 128 + t]);
        float4 v4 = __ldcs(&xrow[(size_t)(i + 4) * 128 + t]);
        float4 v5 = __ldcs(&xrow[(size_t)(i + 5) * 128 + t]);
        float4 v6 = __ldcs(&xrow[(size_t)(i + 6) * 128 + t]);
        float4 v7 = __ldcs(&xrow[(size_t)(i + 7) * 128 + t]);
        a0.x += v0.x; a0.y += v0.y; a0.z += v0.z; a0.w += v0.w;
        a1.x += v1.x; a1.y += v1.y; a1.z += v1.z; a1.w += v1.w;
        a0.x += v2.x; a0.y += v2.y; a0.z += v2.z; a0.w += v2.w;
        a1.x += v3.x; a1.y += v3.y; a1.z += v3.z; a1.w += v3.w;
        a0.x += v4.x; a0.y += v4.y; a0.z += v4.z; a0.w += v4.w;
        a1.x += v5.x; a1.y += v5.y; a1.z += v5.z; a1.w += v5.w;
        a0.x += v6.x; a0.y += v6.y; a0.z += v6.z; a0.w += v6.w;
        a1.x += v7.x; a1.y += v7.y; a1.z += v7.z; a1.w += v7.w;
    }
    a0.x += a1.x; a0.y += a1.y; a0.z += a1.z; a0.w += a1.w;

    float4* p = reinterpret_cast<float4*>(
        g_partial + ((size_t)b * CHUNKS + chunk) * D_DIM);
    p[t] = a0;
}

// ---------------------------------------------------------------------------
// K2 (merged k2a+k2b): per batch, reduce 128 chunk-partials, project, scale.
// grid = B, 512 threads.
//   Phase 1: group g = t>>7 (4 groups), d4 = t&127. Group g sums 32 chunks
//            [32g, 32g+32) -- float4, fully coalesced, L2-hot (64KB/group).
//   Phase 2: smem combine 4 groups -> s_mean.
//   Phase 3: warp w owns d-slice [32w,32w+32); lanes own r (coalesced W).
//   Phase 4: smem reduce 16 warp partials per r, scale by pw.
// ---------------------------------------------------------------------------
__global__ __launch_bounds__(512) void k2_finish_and_project(
    const float* __restrict__ W, const float* __restrict__ pw) {
    __shared__ float s_part[4][D_DIM];
    __shared__ float s_mean[D_DIM];
    __shared__ float s_red[16][R_DIM];
    const int b = blockIdx.x;
    const int t = threadIdx.x;
    const int g  = t >> 7;        // 0..3
    const int d4 = t & 127;       // 0..127

    const float4* pbase = reinterpret_cast<const float4*>(
        g_partial + (size_t)b * CHUNKS * D_DIM);

    float4 acc0 = make_float4(0.f, 0.f, 0.f, 0.f);
    float4 acc1 = make_float4(0.f, 0.f, 0.f, 0.f);
#pragma unroll
    for (int c = g * 32; c < g * 32 + 32; c += 2) {
        float4 v0 = __ldcg(&pbase[(size_t)c * 128 + d4]);
        float4 v1 = __ldcg(&pbase[(size_t)(c + 1) * 128 + d4]);
        acc0.x += v0.x; acc0.y += v0.y; acc0.z += v0.z; acc0.w += v0.w;
        acc1.x += v1.x; acc1.y += v1.y; acc1.z += v1.z; acc1.w += v1.w;
    }
    acc0.x += acc1.x; acc0.y += acc1.y; acc0.z += acc1.z; acc0.w += acc1.w;
    s_part[g][4 * d4 + 0] = acc0.x;
    s_part[g][4 * d4 + 1] = acc0.y;
    s_part[g][4 * d4 + 2] = acc0.z;
    s_part[g][4 * d4 + 3] = acc0.w;
    __syncthreads();

    s_mean[t] = (s_part[0][t] + s_part[1][t] + s_part[2][t] + s_part[3][t])
                * (1.0f / (float)N_DIM);
    __syncthreads();

    const int w    = t >> 5;
    const int lane = t & 31;
    float p0 = 0.f, p1 = 0.f, p2 = 0.f, p3 = 0.f;
#pragma unroll
    for (int i = 0; i < 32; ++i) {
        const int d = w * 32 + i;
        const float m = s_mean[d];
        const float* Wr = W + (size_t)d * R_DIM;
        p0 = fmaf(m, __ldg(&Wr[lane]),      p0);
        p1 = fmaf(m, __ldg(&Wr[32 + lane]), p1);
        p2 = fmaf(m, __ldg(&Wr[64 + lane]), p2);
        p3 = fmaf(m, __ldg(&Wr[96 + lane]), p3);
    }
    s_red[w][lane]      = p0;
    s_red[w][32 + lane] = p1;
    s_red[w][64 + lane] = p2;
    s_red[w][96 + lane] = p3;
    __syncthreads();

    if (t < R_DIM) {
        float y = 0.f;
#pragma unroll
        for (int k = 0; k < 16; ++k)
            y += s_red[k][t];
        g_y[b * R_DIM + t] = y * pw[t];
    }
}

// ---------------------------------------------------------------------------
// K3: broadcast y over the sequence axis. (round-5 proven: 8 STG.128 ILP)
// Thread owns float4 slot tid in every batch; (stride & 31) invariant so v
// is loaded once per batch; 8 independent coalesced STG.128 per thread.
// ---------------------------------------------------------------------------
__global__ __launch_bounds__(256) void k3_broadcast(float4* __restrict__ out) {
    const int tid = blockIdx.x * blockDim.x + threadIdx.x;  // 0..262143
    const int r4  = tid & (R_DIM / 4 - 1);
    const float4* y4 = reinterpret_cast<const float4*>(g_y);
#pragma unroll
    for (int b = 0; b < B_DIM; ++b) {
        float4 v = __ldg(&y4[b * (R_DIM / 4) + r4]);
        out[(size_t)b * (N_DIM * R_DIM / 4) + tid] = v;
    }
}

// ---------------------------------------------------------------------------
extern "C" void kernel_launch(void* const* d_in, const int* in_sizes, int n_in,
                              void* d_out, int out_size) {
    const float* x  = (const float*)d_in[0];
    const float* W  = (const float*)d_in[1];
    const float* pw = (const float*)d_in[2];
    float* out      = (float*)d_out;

    (void)in_sizes; (void)n_in; (void)out_size;

    dim3 g1(CHUNKS, B_DIM);                    // 1024 blocks
    k1_colsum_partial<<<g1, 128>>>(x);

    k2_finish_and_project<<<B_DIM, 512>>>(W, pw);

    const int perBatch4 = N_DIM * R_DIM / 4;   // 262144
    k3_broadcast<<<perBatch4 / 256, 256>>>((float4*)out);
}